// round 6
// baseline (speedup 1.0000x reference)
#include <cuda_runtime.h>

// Problem constants
#define B_  2
#define S_  2048
#define D_  1024
#define H_  16
#define DH_ 64
#define M_  (B_ * S_)   // 4096 rows

// Static device scratch (allocs are forbidden; module-load allocation is fine)
static __device__ float g_q[(size_t)B_ * H_ * S_ * DH_];   // [B,H,S,DH]
static __device__ float g_k[(size_t)B_ * H_ * S_ * DH_];
static __device__ float g_v[(size_t)B_ * H_ * S_ * DH_];
static __device__ float g_ctx[(size_t)B_ * S_ * D_];       // [B,S,H*DH]

// ---------------------------------------------------------------------------
// Fused QKV projection GEMM.
// C[b,h,s,e] = sum_d X[b,s,d] * W[h,d,e] + bias[h,e]
// Viewed as GEMM: M=4096 (m=b*S+s), N=1024 (n=h*64+e), K=1024.
// 128x128 CTA tile, BK=8, 256 threads, 8x8 register tile per thread.
// blockIdx.z selects which of Q/K/V to compute.
// ---------------------------------------------------------------------------
__global__ __launch_bounds__(256) void mha_qkv_gemm(
    const float* __restrict__ Xq, const float* __restrict__ Xk, const float* __restrict__ Xv,
    const float* __restrict__ Wq, const float* __restrict__ Wk, const float* __restrict__ Wv,
    const float* __restrict__ bq, const float* __restrict__ bk, const float* __restrict__ bv)
{
    __shared__ float As[8][128];   // A transposed: As[k][m]
    __shared__ float Bs[8][128];   // Bs[k][n]

    const int sel = blockIdx.z;
    const float* __restrict__ A    = (sel == 0) ? Xq : (sel == 1) ? Xk : Xv;
    const float* __restrict__ W    = (sel == 0) ? Wq : (sel == 1) ? Wk : Wv;
    const float* __restrict__ bias = (sel == 0) ? bq : (sel == 1) ? bk : bv;
    float* __restrict__ Cout       = (sel == 0) ? g_q : (sel == 1) ? g_k : g_v;

    const int tid = threadIdx.x;
    const int m0 = blockIdx.y * 128;
    const int n0 = blockIdx.x * 128;

    // Loader mapping
    const int aRow = tid >> 1;            // 0..127
    const int aCol = (tid & 1) << 2;      // 0 or 4
    const int bRow = tid >> 5;            // 0..7
    const int bCol = (tid & 31) << 2;     // 0..124 (stays inside one 64-wide head)

    // Compute mapping (split 4+4 to avoid smem bank conflicts)
    const int ty4 = (tid >> 4) << 2;      // 0..60
    const int tx4 = (tid & 15) << 2;      // 0..60

    float acc[8][8];
#pragma unroll
    for (int i = 0; i < 8; i++)
#pragma unroll
        for (int j = 0; j < 8; j++) acc[i][j] = 0.f;

    // W[h,d,e] flat: ((n>>6) * 1024*64) + d*64 + (n&63)
    const int nb = n0 + bCol;
    const float* __restrict__ wsrc = W + ((size_t)(nb >> 6) << 16) + (nb & 63);
    const float* __restrict__ asrc = A + (size_t)(m0 + aRow) * D_ + aCol;

    for (int k0 = 0; k0 < D_; k0 += 8) {
        float4 av  = *(const float4*)(asrc + k0);
        float4 bv4 = *(const float4*)(wsrc + (size_t)(k0 + bRow) * DH_);
        As[aCol + 0][aRow] = av.x;
        As[aCol + 1][aRow] = av.y;
        As[aCol + 2][aRow] = av.z;
        As[aCol + 3][aRow] = av.w;
        *(float4*)&Bs[bRow][bCol] = bv4;
        __syncthreads();
#pragma unroll
        for (int kk = 0; kk < 8; kk++) {
            float4 a0 = *(const float4*)&As[kk][ty4];
            float4 a1 = *(const float4*)&As[kk][64 + ty4];
            float4 b0 = *(const float4*)&Bs[kk][tx4];
            float4 b1 = *(const float4*)&Bs[kk][64 + tx4];
            float a[8] = {a0.x, a0.y, a0.z, a0.w, a1.x, a1.y, a1.z, a1.w};
            float b[8] = {b0.x, b0.y, b0.z, b0.w, b1.x, b1.y, b1.z, b1.w};
#pragma unroll
            for (int i = 0; i < 8; i++)
#pragma unroll
                for (int j = 0; j < 8; j++) acc[i][j] += a[i] * b[j];
        }
        __syncthreads();
    }

    // Epilogue: add bias and scatter into [B,H,S,DH]
    float4 bias0 = *(const float4*)(bias + n0 + tx4);
    float4 bias1 = *(const float4*)(bias + n0 + 64 + tx4);
    const int h0 = n0 >> 6;   // n0 is a multiple of 128 -> cols split into heads h0, h0+1

#pragma unroll
    for (int i = 0; i < 8; i++) {
        const int m  = m0 + ((i < 4) ? (ty4 + i) : (64 + ty4 + (i - 4)));
        const int bI = m >> 11;           // batch
        const int sI = m & (S_ - 1);      // seq position
        float4 v0 = make_float4(acc[i][0] + bias0.x, acc[i][1] + bias0.y,
                                acc[i][2] + bias0.z, acc[i][3] + bias0.w);
        float4 v1 = make_float4(acc[i][4] + bias1.x, acc[i][5] + bias1.y,
                                acc[i][6] + bias1.z, acc[i][7] + bias1.w);
        *(float4*)(Cout + ((size_t)(bI * H_ + h0)     * S_ + sI) * DH_ + tx4) = v0;
        *(float4*)(Cout + ((size_t)(bI * H_ + h0 + 1) * S_ + sI) * DH_ + tx4) = v1;
    }
}

// ---------------------------------------------------------------------------
// Flash attention: one query row per thread (q[64], o[64] in registers),
// streaming 64-key chunks through shared memory. Online softmax with
// rescale-on-new-max. All K/V smem reads are warp-broadcast (conflict-free).
// Grid: (S/128, B*H), 128 threads.
// ---------------------------------------------------------------------------
__global__ __launch_bounds__(128) void mha_attn(const int* __restrict__ mask)
{
    __shared__ float Ks[64][64];
    __shared__ float Vs[64][64];
    __shared__ int   msk[64];

    const int tid = threadIdx.x;
    const int bh  = blockIdx.y;            // 0..31
    const int bI  = bh >> 4;
    const int hI  = bh & (H_ - 1);
    const int srow = blockIdx.x * 128 + tid;   // query position (0..2047)

    const float scale = 0.125f;            // 1/sqrt(64)

    const float* __restrict__ qptr  = g_q + ((size_t)bh * S_ + srow) * DH_;
    const float* __restrict__ Kbase = g_k + (size_t)bh * S_ * DH_;
    const float* __restrict__ Vbase = g_v + (size_t)bh * S_ * DH_;

    float q[DH_], o[DH_];
#pragma unroll
    for (int e4 = 0; e4 < DH_ / 4; e4++) {
        float4 qv = *(const float4*)(qptr + e4 * 4);
        q[e4 * 4 + 0] = qv.x * scale;
        q[e4 * 4 + 1] = qv.y * scale;
        q[e4 * 4 + 2] = qv.z * scale;
        q[e4 * 4 + 3] = qv.w * scale;
        o[e4 * 4 + 0] = 0.f; o[e4 * 4 + 1] = 0.f;
        o[e4 * 4 + 2] = 0.f; o[e4 * 4 + 3] = 0.f;
    }
    float mmax = -1e30f, l = 0.f;

    for (int kb = 0; kb < S_; kb += 64) {
        __syncthreads();   // protect smem from previous iteration's readers
        // Cooperative load of K/V chunk: 64x64 floats each = 8 float4 per thread
#pragma unroll
        for (int i = 0; i < 8; i++) {
            int idx4 = tid + i * 128;              // 0..1023 float4 slots
            int r = idx4 >> 4;
            int c = (idx4 & 15) << 2;
            *(float4*)&Ks[r][c] = *(const float4*)(Kbase + (size_t)(kb + r) * DH_ + c);
            *(float4*)&Vs[r][c] = *(const float4*)(Vbase + (size_t)(kb + r) * DH_ + c);
        }
        if (tid < 64) msk[tid] = mask[bI * S_ + kb + tid];
        __syncthreads();

        for (int j = 0; j < 64; j++) {
            const float4* __restrict__ krow = (const float4*)&Ks[j][0];
            float s0 = 0.f, s1 = 0.f, s2 = 0.f, s3 = 0.f;
#pragma unroll
            for (int e4 = 0; e4 < DH_ / 4; e4++) {
                float4 kv = krow[e4];
                s0 += q[e4 * 4 + 0] * kv.x;
                s1 += q[e4 * 4 + 1] * kv.y;
                s2 += q[e4 * 4 + 2] * kv.z;
                s3 += q[e4 * 4 + 3] * kv.w;
            }
            float s = (s0 + s1) + (s2 + s3);
            if (msk[j] == 0) s = -1e9f;

            if (s > mmax) {
                float corr = __expf(mmax - s);
                mmax = s;
                l *= corr;
#pragma unroll
                for (int e = 0; e < DH_; e++) o[e] *= corr;
            }
            float p = __expf(s - mmax);
            l += p;
            const float4* __restrict__ vrow = (const float4*)&Vs[j][0];
#pragma unroll
            for (int e4 = 0; e4 < DH_ / 4; e4++) {
                float4 vv = vrow[e4];
                o[e4 * 4 + 0] += p * vv.x;
                o[e4 * 4 + 1] += p * vv.y;
                o[e4 * 4 + 2] += p * vv.z;
                o[e4 * 4 + 3] += p * vv.w;
            }
        }
    }

    const float inv = 1.f / l;
    float* __restrict__ outp = g_ctx + ((size_t)bI * S_ + srow) * D_ + hI * DH_;
#pragma unroll
    for (int e4 = 0; e4 < DH_ / 4; e4++) {
        float4 ov = make_float4(o[e4 * 4 + 0] * inv, o[e4 * 4 + 1] * inv,
                                o[e4 * 4 + 2] * inv, o[e4 * 4 + 3] * inv);
        *(float4*)(outp + e4 * 4) = ov;
    }
}

// ---------------------------------------------------------------------------
// Output projection: out[m, n] = sum_k ctx[m, k] * Wo[k, n] + bo[n]
// Plain row-major 128x128x8 SGEMM, same structure as the QKV GEMM.
// ---------------------------------------------------------------------------
__global__ __launch_bounds__(256) void mha_out_gemm(
    const float* __restrict__ Wo, const float* __restrict__ bo, float* __restrict__ C)
{
    __shared__ float As[8][128];
    __shared__ float Bs[8][128];

    const float* __restrict__ A = g_ctx;

    const int tid = threadIdx.x;
    const int m0 = blockIdx.y * 128;
    const int n0 = blockIdx.x * 128;

    const int aRow = tid >> 1;
    const int aCol = (tid & 1) << 2;
    const int bRow = tid >> 5;
    const int bCol = (tid & 31) << 2;
    const int ty4 = (tid >> 4) << 2;
    const int tx4 = (tid & 15) << 2;

    float acc[8][8];
#pragma unroll
    for (int i = 0; i < 8; i++)
#pragma unroll
        for (int j = 0; j < 8; j++) acc[i][j] = 0.f;

    const float* __restrict__ asrc = A + (size_t)(m0 + aRow) * D_ + aCol;
    const float* __restrict__ wsrc = Wo + n0 + bCol;

    for (int k0 = 0; k0 < D_; k0 += 8) {
        float4 av  = *(const float4*)(asrc + k0);
        float4 bv4 = *(const float4*)(wsrc + (size_t)(k0 + bRow) * D_);
        As[aCol + 0][aRow] = av.x;
        As[aCol + 1][aRow] = av.y;
        As[aCol + 2][aRow] = av.z;
        As[aCol + 3][aRow] = av.w;
        *(float4*)&Bs[bRow][bCol] = bv4;
        __syncthreads();
#pragma unroll
        for (int kk = 0; kk < 8; kk++) {
            float4 a0 = *(const float4*)&As[kk][ty4];
            float4 a1 = *(const float4*)&As[kk][64 + ty4];
            float4 b0 = *(const float4*)&Bs[kk][tx4];
            float4 b1 = *(const float4*)&Bs[kk][64 + tx4];
            float a[8] = {a0.x, a0.y, a0.z, a0.w, a1.x, a1.y, a1.z, a1.w};
            float b[8] = {b0.x, b0.y, b0.z, b0.w, b1.x, b1.y, b1.z, b1.w};
#pragma unroll
            for (int i = 0; i < 8; i++)
#pragma unroll
                for (int j = 0; j < 8; j++) acc[i][j] += a[i] * b[j];
        }
        __syncthreads();
    }

    float4 bias0 = *(const float4*)(bo + n0 + tx4);
    float4 bias1 = *(const float4*)(bo + n0 + 64 + tx4);

#pragma unroll
    for (int i = 0; i < 8; i++) {
        const int m = m0 + ((i < 4) ? (ty4 + i) : (64 + ty4 + (i - 4)));
        float4 v0 = make_float4(acc[i][0] + bias0.x, acc[i][1] + bias0.y,
                                acc[i][2] + bias0.z, acc[i][3] + bias0.w);
        float4 v1 = make_float4(acc[i][4] + bias1.x, acc[i][5] + bias1.y,
                                acc[i][6] + bias1.z, acc[i][7] + bias1.w);
        *(float4*)(C + (size_t)m * D_ + n0 + tx4)      = v0;
        *(float4*)(C + (size_t)m * D_ + n0 + 64 + tx4) = v1;
    }
}

// ---------------------------------------------------------------------------
// Launch. Inputs (metadata order):
// 0 query, 1 key, 2 value, 3 mask(int32), 4 Wq, 5 bq, 6 Wk, 7 bk,
// 8 Wv, 9 bv, 10 Wo, 11 bo. Output: [B,S,D] float32.
// ---------------------------------------------------------------------------
extern "C" void kernel_launch(void* const* d_in, const int* in_sizes, int n_in,
                              void* d_out, int out_size)
{
    const float* query = (const float*)d_in[0];
    const float* key   = (const float*)d_in[1];
    const float* value = (const float*)d_in[2];
    const int*   mask  = (const int*)d_in[3];
    const float* Wq    = (const float*)d_in[4];
    const float* bq    = (const float*)d_in[5];
    const float* Wk    = (const float*)d_in[6];
    const float* bk    = (const float*)d_in[7];
    const float* Wv    = (const float*)d_in[8];
    const float* bv    = (const float*)d_in[9];
    const float* Wo    = (const float*)d_in[10];
    const float* bo    = (const float*)d_in[11];
    float* out = (float*)d_out;

    dim3 gQKV(D_ / 128, M_ / 128, 3);   // (8, 32, 3)
    mha_qkv_gemm<<<gQKV, 256>>>(query, key, value, Wq, Wk, Wv, bq, bk, bv);

    dim3 gAtt(S_ / 128, B_ * H_);       // (16, 32)
    mha_attn<<<gAtt, 128>>>(mask);

    dim3 gOut(D_ / 128, M_ / 128);      // (8, 32)
    mha_out_gemm<<<gOut, 256>>>(Wo, bo, out);
}

// round 8
// speedup vs baseline: 1.0778x; 1.0778x over previous
#include <cuda_runtime.h>

// Problem constants
#define B_  2
#define S_  2048
#define D_  1024
#define H_  16
#define DH_ 64
#define M_  (B_ * S_)   // 4096 rows

typedef unsigned long long u64;

// ---- packed fp32x2 helpers (Blackwell-only; ptxas never emits FFMA2 from C++) ----
__device__ __forceinline__ u64 pk2(float lo, float hi) {
    u64 r; asm("mov.b64 %0, {%1, %2};" : "=l"(r) : "f"(lo), "f"(hi)); return r;
}
__device__ __forceinline__ void upk2(float& lo, float& hi, u64 v) {
    asm("mov.b64 {%0, %1}, %2;" : "=f"(lo), "=f"(hi) : "l"(v));
}
__device__ __forceinline__ void fma2(u64& d, u64 a, u64 b) {
    asm("fma.rn.f32x2 %0, %1, %2, %0;" : "+l"(d) : "l"(a), "l"(b));
}
__device__ __forceinline__ u64 mul2(u64 a, u64 b) {
    u64 r; asm("mul.rn.f32x2 %0, %1, %2;" : "=l"(r) : "l"(a), "l"(b)); return r;
}

// Static device scratch (allocs are forbidden)
static __device__ float g_q[(size_t)B_ * H_ * S_ * DH_];   // [B,H,S,DH]
static __device__ float g_k[(size_t)B_ * H_ * S_ * DH_];
static __device__ float g_v[(size_t)B_ * H_ * S_ * DH_];
static __device__ float g_ctx[(size_t)B_ * S_ * D_];       // [B,S,H*DH]

// ---------------------------------------------------------------------------
// Fused QKV projection GEMM.  M=4096, N=1024 (n=h*64+e), K=1024.
// 128x128 CTA tile, BK=16, 256 threads, 8x8 register tile (packed f32x2).
// blockIdx.z selects Q/K/V.
// ---------------------------------------------------------------------------
__global__ __launch_bounds__(256) void mha_qkv_gemm(
    const float* __restrict__ Xq, const float* __restrict__ Xk, const float* __restrict__ Xv,
    const float* __restrict__ Wq, const float* __restrict__ Wk, const float* __restrict__ Wv,
    const float* __restrict__ bq, const float* __restrict__ bk, const float* __restrict__ bv)
{
    __shared__ float As[16][128];   // A transposed: As[k][m]
    __shared__ float Bs[16][128];   // Bs[k][n]

    const int sel = blockIdx.z;
    const float* __restrict__ A    = (sel == 0) ? Xq : (sel == 1) ? Xk : Xv;
    const float* __restrict__ W    = (sel == 0) ? Wq : (sel == 1) ? Wk : Wv;
    const float* __restrict__ bias = (sel == 0) ? bq : (sel == 1) ? bk : bv;
    float* __restrict__ Cout       = (sel == 0) ? g_q : (sel == 1) ? g_k : g_v;

    const int tid = threadIdx.x;
    const int m0 = blockIdx.y * 128;
    const int n0 = blockIdx.x * 128;

    // Loader mapping (BK=16): A tile 128x16, B tile 16x128; 8 floats each/thread
    const int aRow = tid >> 1;            // 0..127
    const int aCol = (tid & 1) << 3;      // 0 or 8
    const int bRow = tid >> 4;            // 0..15
    const int bCol = (tid & 15) << 3;     // 0..120 (8-col group, stays in one head)

    // Compute mapping
    const int ty4 = (tid >> 4) << 2;      // 0..60
    const int tx4 = (tid & 15) << 2;      // 0..60

    u64 acc2[8][4];
#pragma unroll
    for (int i = 0; i < 8; i++)
#pragma unroll
        for (int j = 0; j < 4; j++) acc2[i][j] = 0ull;

    // W[h,d,e] flat: ((n>>6) * 1024*64) + d*64 + (n&63)
    const int nb = n0 + bCol;
    const float* __restrict__ wsrc = W + ((size_t)(nb >> 6) << 16) + (nb & 63);
    const float* __restrict__ asrc = A + (size_t)(m0 + aRow) * D_ + aCol;

    for (int k0 = 0; k0 < D_; k0 += 16) {
        float4 av0 = *(const float4*)(asrc + k0);
        float4 av1 = *(const float4*)(asrc + k0 + 4);
        float4 bw0 = *(const float4*)(wsrc + (size_t)(k0 + bRow) * DH_);
        float4 bw1 = *(const float4*)(wsrc + (size_t)(k0 + bRow) * DH_ + 4);
        As[aCol + 0][aRow] = av0.x;  As[aCol + 1][aRow] = av0.y;
        As[aCol + 2][aRow] = av0.z;  As[aCol + 3][aRow] = av0.w;
        As[aCol + 4][aRow] = av1.x;  As[aCol + 5][aRow] = av1.y;
        As[aCol + 6][aRow] = av1.z;  As[aCol + 7][aRow] = av1.w;
        *(float4*)&Bs[bRow][bCol]     = bw0;
        *(float4*)&Bs[bRow][bCol + 4] = bw1;
        __syncthreads();
#pragma unroll
        for (int kk = 0; kk < 16; kk++) {
            float4 a0 = *(const float4*)&As[kk][ty4];
            float4 a1 = *(const float4*)&As[kk][64 + ty4];
            float4 b0 = *(const float4*)&Bs[kk][tx4];
            float4 b1 = *(const float4*)&Bs[kk][64 + tx4];
            u64 bp[4] = { pk2(b0.x, b0.y), pk2(b0.z, b0.w),
                          pk2(b1.x, b1.y), pk2(b1.z, b1.w) };
            float av[8] = {a0.x, a0.y, a0.z, a0.w, a1.x, a1.y, a1.z, a1.w};
#pragma unroll
            for (int i = 0; i < 8; i++) {
                u64 ad = pk2(av[i], av[i]);
#pragma unroll
                for (int j = 0; j < 4; j++) fma2(acc2[i][j], ad, bp[j]);
            }
        }
        __syncthreads();
    }

    // Epilogue: unpack, add bias, scatter into [B,H,S,DH]
    float4 bias0 = *(const float4*)(bias + n0 + tx4);
    float4 bias1 = *(const float4*)(bias + n0 + 64 + tx4);
    const int h0 = n0 >> 6;

#pragma unroll
    for (int i = 0; i < 8; i++) {
        const int m  = m0 + ((i < 4) ? (ty4 + i) : (64 + ty4 + (i - 4)));
        const int bI = m >> 11;
        const int sI = m & (S_ - 1);
        float c0, c1, c2, c3, c4, c5, c6, c7;
        upk2(c0, c1, acc2[i][0]);  upk2(c2, c3, acc2[i][1]);
        upk2(c4, c5, acc2[i][2]);  upk2(c6, c7, acc2[i][3]);
        float4 v0 = make_float4(c0 + bias0.x, c1 + bias0.y, c2 + bias0.z, c3 + bias0.w);
        float4 v1 = make_float4(c4 + bias1.x, c5 + bias1.y, c6 + bias1.z, c7 + bias1.w);
        *(float4*)(Cout + ((size_t)(bI * H_ + h0)     * S_ + sI) * DH_ + tx4) = v0;
        *(float4*)(Cout + ((size_t)(bI * H_ + h0 + 1) * S_ + sI) * DH_ + tx4) = v1;
    }
}

// ---------------------------------------------------------------------------
// Flash attention: one query row per thread, q/o held as 32 packed f32x2
// pairs; online softmax with rescale-on-new-max. K/V smem reads broadcast.
// Grid: (S/128, B*H), 128 threads.
// ---------------------------------------------------------------------------
__global__ __launch_bounds__(128) void mha_attn(const int* __restrict__ mask)
{
    __shared__ float Ks[64][64];
    __shared__ float Vs[64][64];
    __shared__ int   msk[64];

    const int tid = threadIdx.x;
    const int bh  = blockIdx.y;            // 0..31
    const int bI  = bh >> 4;
    const int hI  = bh & (H_ - 1);
    const int srow = blockIdx.x * 128 + tid;

    const float scale = 0.125f;            // 1/sqrt(64)

    const float* __restrict__ qptr  = g_q + ((size_t)bh * S_ + srow) * DH_;
    const float* __restrict__ Kbase = g_k + (size_t)bh * S_ * DH_;
    const float* __restrict__ Vbase = g_v + (size_t)bh * S_ * DH_;

    u64 q2[32], o2[32];
    const u64 zz = pk2(0.f, 0.f);
#pragma unroll
    for (int e4 = 0; e4 < 16; e4++) {
        float4 qv = *(const float4*)(qptr + e4 * 4);
        q2[e4 * 2 + 0] = pk2(qv.x * scale, qv.y * scale);
        q2[e4 * 2 + 1] = pk2(qv.z * scale, qv.w * scale);
        o2[e4 * 2 + 0] = zz;
        o2[e4 * 2 + 1] = zz;
    }
    float mmax = -1e30f, l = 0.f;

    for (int kb = 0; kb < S_; kb += 64) {
        __syncthreads();   // protect smem from previous iteration's readers
#pragma unroll
        for (int i = 0; i < 8; i++) {
            int idx4 = tid + i * 128;
            int r = idx4 >> 4;
            int c = (idx4 & 15) << 2;
            *(float4*)&Ks[r][c] = *(const float4*)(Kbase + (size_t)(kb + r) * DH_ + c);
            *(float4*)&Vs[r][c] = *(const float4*)(Vbase + (size_t)(kb + r) * DH_ + c);
        }
        if (tid < 64) msk[tid] = mask[bI * S_ + kb + tid];
        __syncthreads();

        for (int j = 0; j < 64; j++) {
            const float4* __restrict__ krow = (const float4*)&Ks[j][0];
            u64 sa = zz, sb = zz, sc = zz, sd = zz;
#pragma unroll
            for (int e4 = 0; e4 < 16; e4 += 2) {
                float4 k0 = krow[e4];
                float4 k1 = krow[e4 + 1];
                fma2(sa, q2[e4 * 2 + 0], pk2(k0.x, k0.y));
                fma2(sb, q2[e4 * 2 + 1], pk2(k0.z, k0.w));
                fma2(sc, q2[e4 * 2 + 2], pk2(k1.x, k1.y));
                fma2(sd, q2[e4 * 2 + 3], pk2(k1.z, k1.w));
            }
            float x0, x1, y0, y1, z0, z1, w0, w1;
            upk2(x0, x1, sa); upk2(y0, y1, sb);
            upk2(z0, z1, sc); upk2(w0, w1, sd);
            float s = ((x0 + x1) + (y0 + y1)) + ((z0 + z1) + (w0 + w1));
            if (msk[j] == 0) s = -1e9f;

            if (s > mmax) {
                float corr = __expf(mmax - s);
                mmax = s;
                l *= corr;
                u64 cd = pk2(corr, corr);
#pragma unroll
                for (int e = 0; e < 32; e++) o2[e] = mul2(o2[e], cd);
            }
            float p = __expf(s - mmax);
            l += p;
            u64 pd = pk2(p, p);
            const float4* __restrict__ vrow = (const float4*)&Vs[j][0];
#pragma unroll
            for (int e4 = 0; e4 < 16; e4++) {
                float4 vv = vrow[e4];
                fma2(o2[e4 * 2 + 0], pd, pk2(vv.x, vv.y));
                fma2(o2[e4 * 2 + 1], pd, pk2(vv.z, vv.w));
            }
        }
    }

    const float inv = 1.f / l;
    float* __restrict__ outp = g_ctx + ((size_t)bI * S_ + srow) * D_ + hI * DH_;
#pragma unroll
    for (int e4 = 0; e4 < 16; e4++) {
        float a0, a1, b0v, b1v;
        upk2(a0, a1, o2[e4 * 2 + 0]);
        upk2(b0v, b1v, o2[e4 * 2 + 1]);
        float4 ov = make_float4(a0 * inv, a1 * inv, b0v * inv, b1v * inv);
        *(float4*)(outp + e4 * 4) = ov;
    }
}

// ---------------------------------------------------------------------------
// Output projection: out = ctx @ Wo + bo.  Same 128x128xBK16 structure.
// ---------------------------------------------------------------------------
__global__ __launch_bounds__(256) void mha_out_gemm(
    const float* __restrict__ Wo, const float* __restrict__ bo, float* __restrict__ C)
{
    __shared__ float As[16][128];
    __shared__ float Bs[16][128];

    const float* __restrict__ A = g_ctx;

    const int tid = threadIdx.x;
    const int m0 = blockIdx.y * 128;
    const int n0 = blockIdx.x * 128;

    const int aRow = tid >> 1;
    const int aCol = (tid & 1) << 3;
    const int bRow = tid >> 4;
    const int bCol = (tid & 15) << 3;
    const int ty4 = (tid >> 4) << 2;
    const int tx4 = (tid & 15) << 2;

    u64 acc2[8][4];
#pragma unroll
    for (int i = 0; i < 8; i++)
#pragma unroll
        for (int j = 0; j < 4; j++) acc2[i][j] = 0ull;

    const float* __restrict__ asrc = A + (size_t)(m0 + aRow) * D_ + aCol;
    const float* __restrict__ wsrc = Wo + n0 + bCol;

    for (int k0 = 0; k0 < D_; k0 += 16) {
        float4 av0 = *(const float4*)(asrc + k0);
        float4 av1 = *(const float4*)(asrc + k0 + 4);
        float4 bw0 = *(const float4*)(wsrc + (size_t)(k0 + bRow) * D_);
        float4 bw1 = *(const float4*)(wsrc + (size_t)(k0 + bRow) * D_ + 4);
        As[aCol + 0][aRow] = av0.x;  As[aCol + 1][aRow] = av0.y;
        As[aCol + 2][aRow] = av0.z;  As[aCol + 3][aRow] = av0.w;
        As[aCol + 4][aRow] = av1.x;  As[aCol + 5][aRow] = av1.y;
        As[aCol + 6][aRow] = av1.z;  As[aCol + 7][aRow] = av1.w;
        *(float4*)&Bs[bRow][bCol]     = bw0;
        *(float4*)&Bs[bRow][bCol + 4] = bw1;
        __syncthreads();
#pragma unroll
        for (int kk = 0; kk < 16; kk++) {
            float4 a0 = *(const float4*)&As[kk][ty4];
            float4 a1 = *(const float4*)&As[kk][64 + ty4];
            float4 b0 = *(const float4*)&Bs[kk][tx4];
            float4 b1 = *(const float4*)&Bs[kk][64 + tx4];
            u64 bp[4] = { pk2(b0.x, b0.y), pk2(b0.z, b0.w),
                          pk2(b1.x, b1.y), pk2(b1.z, b1.w) };
            float av[8] = {a0.x, a0.y, a0.z, a0.w, a1.x, a1.y, a1.z, a1.w};
#pragma unroll
            for (int i = 0; i < 8; i++) {
                u64 ad = pk2(av[i], av[i]);
#pragma unroll
                for (int j = 0; j < 4; j++) fma2(acc2[i][j], ad, bp[j]);
            }
        }
        __syncthreads();
    }

    float4 bias0 = *(const float4*)(bo + n0 + tx4);
    float4 bias1 = *(const float4*)(bo + n0 + 64 + tx4);

#pragma unroll
    for (int i = 0; i < 8; i++) {
        const int m = m0 + ((i < 4) ? (ty4 + i) : (64 + ty4 + (i - 4)));
        float c0, c1, c2, c3, c4, c5, c6, c7;
        upk2(c0, c1, acc2[i][0]);  upk2(c2, c3, acc2[i][1]);
        upk2(c4, c5, acc2[i][2]);  upk2(c6, c7, acc2[i][3]);
        float4 v0 = make_float4(c0 + bias0.x, c1 + bias0.y, c2 + bias0.z, c3 + bias0.w);
        float4 v1 = make_float4(c4 + bias1.x, c5 + bias1.y, c6 + bias1.z, c7 + bias1.w);
        *(float4*)(C + (size_t)m * D_ + n0 + tx4)      = v0;
        *(float4*)(C + (size_t)m * D_ + n0 + 64 + tx4) = v1;
    }
}

// ---------------------------------------------------------------------------
// Launch. Inputs (metadata order):
// 0 query, 1 key, 2 value, 3 mask(int32), 4 Wq, 5 bq, 6 Wk, 7 bk,
// 8 Wv, 9 bv, 10 Wo, 11 bo. Output: [B,S,D] float32.
// ---------------------------------------------------------------------------
extern "C" void kernel_launch(void* const* d_in, const int* in_sizes, int n_in,
                              void* d_out, int out_size)
{
    const float* query = (const float*)d_in[0];
    const float* key   = (const float*)d_in[1];
    const float* value = (const float*)d_in[2];
    const int*   mask  = (const int*)d_in[3];
    const float* Wq    = (const float*)d_in[4];
    const float* bq    = (const float*)d_in[5];
    const float* Wk    = (const float*)d_in[6];
    const float* bk    = (const float*)d_in[7];
    const float* Wv    = (const float*)d_in[8];
    const float* bv    = (const float*)d_in[9];
    const float* Wo    = (const float*)d_in[10];
    const float* bo    = (const float*)d_in[11];
    float* out = (float*)d_out;

    dim3 gQKV(D_ / 128, M_ / 128, 3);   // (8, 32, 3)
    mha_qkv_gemm<<<gQKV, 256>>>(query, key, value, Wq, Wk, Wv, bq, bk, bv);

    dim3 gAtt(S_ / 128, B_ * H_);       // (16, 32)
    mha_attn<<<gAtt, 128>>>(mask);

    dim3 gOut(D_ / 128, M_ / 128);      // (8, 32)
    mha_out_gemm<<<gOut, 256>>>(Wo, bo, out);
}